// round 5
// baseline (speedup 1.0000x reference)
#include <cuda_runtime.h>
#include <cstdint>

#define THRESH      0.7f
#define MIN_KEPT    100000
#define IGNORE_LBL  (-100.0f)
#define LOG_CLAMP   (-100.0f)

// ---------------- device state (reset every launch by k_init) ----------------
__device__ double        g_sum_lt;          // loss sum: valid & p < 0.7
__device__ double        g_sum_mid;         // loss sum: valid & 0.7 <= p < T (refine path)
__device__ int           g_cnt_valid;
__device__ int           g_cnt_lt;          // valid & p < 0.7
__device__ int           g_cnt_eq;          // valid & p == 0.7 (decides threshold==0.7 case exactly)
__device__ int           g_cnt_mid;
__device__ int           g_flag;            // 1 => refinement path active
__device__ int           g_rank_hi;         // rank within the p>=0.7 region
__device__ int           g_rank_lo;
__device__ unsigned int  g_bin_hi;
__device__ float         g_T;               // exact k-th smallest (refine path)
__device__ unsigned int  g_hist_hi[65536];
__device__ unsigned int  g_hist_lo[65536];

// ------------------------------- helpers ------------------------------------
__device__ __forceinline__ float bce(float p, float t, float w) {
    // torch binary_cross_entropy semantics with log clamp at -100.
    // Only evaluated where it contributes; selected elems have p < threshold,
    // and on the hot path p < 0.7 so (1-p) > 0.3 => __logf(1-p) is accurate.
    float lp = fmaxf(__logf(p),        LOG_CLAMP);
    float l1 = fmaxf(__logf(1.0f - p), LOG_CLAMP);
    return -w * (t * lp + (1.0f - t) * l1);
}

__global__ void k_init() {
    int i = blockIdx.x * blockDim.x + threadIdx.x;
    int stride = gridDim.x * blockDim.x;
    for (int j = i; j < 65536; j += stride) { g_hist_hi[j] = 0u; g_hist_lo[j] = 0u; }
    if (i == 0) {
        g_sum_lt = 0.0; g_sum_mid = 0.0;
        g_cnt_valid = 0; g_cnt_lt = 0; g_cnt_eq = 0; g_cnt_mid = 0;
        g_flag = 0; g_rank_hi = 0; g_rank_lo = 0; g_bin_hi = 0u; g_T = 0.0f;
    }
}

// --------------------- main fused streaming pass (hot path) ------------------
__global__ void __launch_bounds__(256) k_pass1(
    const float* __restrict__ P, const float* __restrict__ T,
    const float* __restrict__ W, int n)
{
    int tid    = blockIdx.x * blockDim.x + threadIdx.x;
    int stride = gridDim.x * blockDim.x;
    int nvec   = n >> 2;

    const float4* __restrict__ P4 = (const float4*)P;
    const float4* __restrict__ T4 = (const float4*)T;
    const float4* __restrict__ W4 = (const float4*)W;

    float sum = 0.0f;
    int cv = 0, clt = 0, ceq = 0;

    for (int i = tid; i < nvec; i += stride) {
        float4 p = P4[i];
        float4 t = T4[i];
        float4 w = W4[i];
#define LANE(px, tx, wx)                                         \
        if ((tx) != IGNORE_LBL) {                                \
            cv++;                                                \
            if ((px) < THRESH)      { clt++; sum += bce((px),(tx),(wx)); } \
            else if ((px) == THRESH) ceq++;                      \
        }
        LANE(p.x, t.x, w.x)
        LANE(p.y, t.y, w.y)
        LANE(p.z, t.z, w.z)
        LANE(p.w, t.w, w.w)
#undef LANE
    }
    // scalar tail (n not multiple of 4)
    for (int i = (nvec << 2) + tid; i < n; i += stride) {
        float pv = P[i], tv = T[i], wv = W[i];
        if (tv != IGNORE_LBL) {
            cv++;
            if (pv < THRESH)      { clt++; sum += bce(pv, tv, wv); }
            else if (pv == THRESH) ceq++;
        }
    }

    // block reduction: warp shuffles -> shared -> one atomic set per block
    unsigned full = 0xFFFFFFFFu;
    for (int o = 16; o; o >>= 1) {
        sum += __shfl_down_sync(full, sum, o);
        cv  += __shfl_down_sync(full, cv,  o);
        clt += __shfl_down_sync(full, clt, o);
        ceq += __shfl_down_sync(full, ceq, o);
    }
    __shared__ float ss[8];
    __shared__ int   sv[8], sl[8], se[8];
    int lane = threadIdx.x & 31, wid = threadIdx.x >> 5;
    if (lane == 0) { ss[wid] = sum; sv[wid] = cv; sl[wid] = clt; se[wid] = ceq; }
    __syncthreads();
    if (wid == 0) {
        int nw = blockDim.x >> 5;
        sum = (lane < nw) ? ss[lane] : 0.0f;
        cv  = (lane < nw) ? sv[lane] : 0;
        clt = (lane < nw) ? sl[lane] : 0;
        ceq = (lane < nw) ? se[lane] : 0;
        for (int o = 4; o; o >>= 1) {
            sum += __shfl_down_sync(full, sum, o);
            cv  += __shfl_down_sync(full, cv,  o);
            clt += __shfl_down_sync(full, clt, o);
            ceq += __shfl_down_sync(full, ceq, o);
        }
        if (lane == 0) {
            atomicAdd(&g_sum_lt, (double)sum);
            atomicAdd(&g_cnt_valid, cv);
            atomicAdd(&g_cnt_lt, clt);
            if (ceq) atomicAdd(&g_cnt_eq, ceq);
        }
    }
}

// ------------------------------ decision ------------------------------------
__global__ void k_decide(float* out) {
    long long nv = (long long)g_cnt_valid;
    long long k  = nv - 1;
    if (k > (long long)MIN_KEPT) k = MIN_KEPT;
    // sort_p[k] <= 0.7  <=>  count(valid & p <= 0.7) >= k+1  => threshold == 0.7
    if ((long long)g_cnt_lt + (long long)g_cnt_eq >= k + 1) {
        g_flag = 0;
        out[0] = (float)(g_sum_lt / (double)g_cnt_lt);
    } else {
        g_flag = 1;
        g_rank_hi = (int)(k - (long long)g_cnt_lt);  // rank within p >= 0.7 region
    }
}

// ---------------- refinement path (flag-guarded, early-exits) ----------------
__global__ void k_hist_hi(const float* __restrict__ P, const float* __restrict__ T, int n) {
    if (!g_flag) return;
    int tid = blockIdx.x * blockDim.x + threadIdx.x;
    int stride = gridDim.x * blockDim.x;
    for (int i = tid; i < n; i += stride) {
        float tv = T[i], pv = P[i];
        if (tv != IGNORE_LBL && pv >= THRESH)
            atomicAdd(&g_hist_hi[__float_as_uint(pv) >> 16], 1u);
    }
}

__global__ void k_find_hi() {
    if (!g_flag) return;
    unsigned cum = 0, r = (unsigned)g_rank_hi;
    for (int b = 0; b < 65536; b++) {
        unsigned c = g_hist_hi[b];
        if (cum + c > r) { g_bin_hi = (unsigned)b; g_rank_lo = (int)(r - cum); return; }
        cum += c;
    }
}

__global__ void k_hist_lo(const float* __restrict__ P, const float* __restrict__ T, int n) {
    if (!g_flag) return;
    unsigned bh = g_bin_hi;
    int tid = blockIdx.x * blockDim.x + threadIdx.x;
    int stride = gridDim.x * blockDim.x;
    for (int i = tid; i < n; i += stride) {
        float tv = T[i], pv = P[i];
        if (tv != IGNORE_LBL && pv >= THRESH) {
            unsigned b = __float_as_uint(pv);
            if ((b >> 16) == bh) atomicAdd(&g_hist_lo[b & 0xFFFFu], 1u);
        }
    }
}

__global__ void k_find_lo() {
    if (!g_flag) return;
    unsigned cum = 0, r = (unsigned)g_rank_lo;
    for (int l = 0; l < 65536; l++) {
        unsigned c = g_hist_lo[l];
        if (cum + c > r) { g_T = __uint_as_float((g_bin_hi << 16) | (unsigned)l); return; }
        cum += c;
    }
}

__global__ void __launch_bounds__(256) k_mid(
    const float* __restrict__ P, const float* __restrict__ T,
    const float* __restrict__ W, int n)
{
    if (!g_flag) return;   // uniform across the block: safe w.r.t. barriers below
    float Tv = g_T;
    int tid = blockIdx.x * blockDim.x + threadIdx.x;
    int stride = gridDim.x * blockDim.x;
    float sum = 0.0f; int cnt = 0;
    for (int i = tid; i < n; i += stride) {
        float tv = T[i], pv = P[i];
        if (tv != IGNORE_LBL && pv >= THRESH && pv < Tv) {
            sum += bce(pv, tv, W[i]);
            cnt++;
        }
    }
    unsigned full = 0xFFFFFFFFu;
    for (int o = 16; o; o >>= 1) {
        sum += __shfl_down_sync(full, sum, o);
        cnt += __shfl_down_sync(full, cnt, o);
    }
    __shared__ float ss[8];
    __shared__ int   sc[8];
    int lane = threadIdx.x & 31, wid = threadIdx.x >> 5;
    if (lane == 0) { ss[wid] = sum; sc[wid] = cnt; }
    __syncthreads();
    if (wid == 0) {
        int nw = blockDim.x >> 5;
        sum = (lane < nw) ? ss[lane] : 0.0f;
        cnt = (lane < nw) ? sc[lane] : 0;
        for (int o = 4; o; o >>= 1) {
            sum += __shfl_down_sync(full, sum, o);
            cnt += __shfl_down_sync(full, cnt, o);
        }
        if (lane == 0) {
            atomicAdd(&g_sum_mid, (double)sum);
            atomicAdd(&g_cnt_mid, cnt);
        }
    }
}

__global__ void k_final(float* out) {
    if (!g_flag) return;
    out[0] = (float)((g_sum_lt + g_sum_mid) / (double)(g_cnt_lt + g_cnt_mid));
}

// ------------------------------- launcher -----------------------------------
extern "C" void kernel_launch(void* const* d_in, const int* in_sizes, int n_in,
                              void* d_out, int out_size)
{
    const float* P = (const float*)d_in[0];   // predict
    const float* T = (const float*)d_in[1];   // target
    const float* W = (const float*)d_in[2];   // weight
    float* out = (float*)d_out;
    int n = in_sizes[0];

    k_init<<<64, 256>>>();

    int nvec = n >> 2;
    int blocks = (nvec + 255) / 256;
    if (blocks > 4096) blocks = 4096;
    if (blocks < 1) blocks = 1;
    k_pass1<<<blocks, 256>>>(P, T, W, n);

    k_decide<<<1, 1>>>(out);

    int rb = (n + 255) / 256;
    if (rb > 1024) rb = 1024;
    if (rb < 1) rb = 1;
    k_hist_hi<<<rb, 256>>>(P, T, n);
    k_find_hi<<<1, 1>>>();
    k_hist_lo<<<rb, 256>>>(P, T, n);
    k_find_lo<<<1, 1>>>();
    k_mid<<<rb, 256>>>(P, T, W, n);
    k_final<<<1, 1>>>(out);
}

// round 7
// speedup vs baseline: 1.0696x; 1.0696x over previous
#include <cuda_runtime.h>
#include <cstdint>

#define THRESH      0.7f
#define MIN_KEPT    100000
#define IGNORE_LBL  (-100.0f)
#define LOG_CLAMP   (-100.0f)

// ---------------- device state (reset-after-use; zero-init at load) ----------
__device__ double        g_sum_lt   = 0.0;   // loss sum: valid & p < 0.7
__device__ int           g_cnt_valid = 0;
__device__ int           g_cnt_lt   = 0;     // valid & p < 0.7
__device__ int           g_cnt_eq   = 0;     // valid & p == 0.7
__device__ int           g_flag     = 0;     // 1 => refinement path active
__device__ int           g_rank_hi  = 0;     // rank within the p>=0.7 region
__device__ unsigned int  g_done     = 0;     // block retirement counter
__device__ unsigned int  g_hist_hi[65536];   // only touched on refine path
__device__ unsigned int  g_hist_lo[65536];   // (zeroed inside k_refine)

// ------------------------------- helpers ------------------------------------
__device__ __forceinline__ float bce(float p, float t, float w) {
    // torch binary_cross_entropy semantics with log clamp at -100.
    // Hot path only evaluates this for p < 0.7, so (1-p) > 0.3 and __logf
    // is well inside the 1e-3 tolerance.
    float lp = fmaxf(__logf(p),        LOG_CLAMP);
    float l1 = fmaxf(__logf(1.0f - p), LOG_CLAMP);
    return -w * (t * lp + (1.0f - t) * l1);
}

// --------------------- main fused streaming pass (hot path) ------------------
// Includes the decision epilogue in the last retiring block, so no separate
// init/decide kernels are needed. All accumulators are reset after use so the
// kernel is graph-replay deterministic.
__global__ void __launch_bounds__(256) k_pass1(
    const float* __restrict__ P, const float* __restrict__ T,
    const float* __restrict__ W, float* __restrict__ out, int n)
{
    const int tid    = blockIdx.x * blockDim.x + threadIdx.x;
    const int stride = gridDim.x * blockDim.x;
    const int nvec   = n >> 2;

    const float4* __restrict__ P4 = (const float4*)P;
    const float4* __restrict__ T4 = (const float4*)T;
    const float4* __restrict__ W4 = (const float4*)W;

    float sum = 0.0f;
    int cv = 0, clt = 0, ceq = 0;

#define LANE(px, tx, wx)                                                   \
    if ((tx) != IGNORE_LBL) {                                              \
        cv++;                                                              \
        if ((px) < THRESH)       { clt++; sum += bce((px),(tx),(wx)); }    \
        else if ((px) == THRESH) ceq++;                                    \
    }

    int i = tid;
    // unrolled-by-4 body: 12 independent float4 loads in flight per iteration
    for (; i + 3 * stride < nvec; i += 4 * stride) {
        float4 p0 = P4[i];              float4 p1 = P4[i + stride];
        float4 p2 = P4[i + 2 * stride]; float4 p3 = P4[i + 3 * stride];
        float4 t0 = T4[i];              float4 t1 = T4[i + stride];
        float4 t2 = T4[i + 2 * stride]; float4 t3 = T4[i + 3 * stride];
        float4 w0 = W4[i];              float4 w1 = W4[i + stride];
        float4 w2 = W4[i + 2 * stride]; float4 w3 = W4[i + 3 * stride];
        LANE(p0.x, t0.x, w0.x) LANE(p0.y, t0.y, w0.y) LANE(p0.z, t0.z, w0.z) LANE(p0.w, t0.w, w0.w)
        LANE(p1.x, t1.x, w1.x) LANE(p1.y, t1.y, w1.y) LANE(p1.z, t1.z, w1.z) LANE(p1.w, t1.w, w1.w)
        LANE(p2.x, t2.x, w2.x) LANE(p2.y, t2.y, w2.y) LANE(p2.z, t2.z, w2.z) LANE(p2.w, t2.w, w2.w)
        LANE(p3.x, t3.x, w3.x) LANE(p3.y, t3.y, w3.y) LANE(p3.z, t3.z, w3.z) LANE(p3.w, t3.w, w3.w)
    }
    for (; i < nvec; i += stride) {
        float4 p = P4[i]; float4 t = T4[i]; float4 w = W4[i];
        LANE(p.x, t.x, w.x) LANE(p.y, t.y, w.y) LANE(p.z, t.z, w.z) LANE(p.w, t.w, w.w)
    }
    // scalar tail (n not multiple of 4)
    for (int j = (nvec << 2) + tid; j < n; j += stride) {
        float pv = P[j], tv = T[j], wv = W[j];
        LANE(pv, tv, wv)
    }
#undef LANE

    // block reduction: warp shuffles -> shared -> per-block atomics
    const unsigned full = 0xFFFFFFFFu;
    for (int o = 16; o; o >>= 1) {
        sum += __shfl_down_sync(full, sum, o);
        cv  += __shfl_down_sync(full, cv,  o);
        clt += __shfl_down_sync(full, clt, o);
        ceq += __shfl_down_sync(full, ceq, o);
    }
    __shared__ float ss[8];
    __shared__ int   sv[8], sl[8], se[8];
    int lane = threadIdx.x & 31, wid = threadIdx.x >> 5;
    if (lane == 0) { ss[wid] = sum; sv[wid] = cv; sl[wid] = clt; se[wid] = ceq; }
    __syncthreads();
    if (wid == 0) {
        int nw = blockDim.x >> 5;
        sum = (lane < nw) ? ss[lane] : 0.0f;
        cv  = (lane < nw) ? sv[lane] : 0;
        clt = (lane < nw) ? sl[lane] : 0;
        ceq = (lane < nw) ? se[lane] : 0;
        for (int o = 4; o; o >>= 1) {
            sum += __shfl_down_sync(full, sum, o);
            cv  += __shfl_down_sync(full, cv,  o);
            clt += __shfl_down_sync(full, clt, o);
            ceq += __shfl_down_sync(full, ceq, o);
        }
        if (lane == 0) {
            atomicAdd(&g_sum_lt, (double)sum);
            atomicAdd(&g_cnt_valid, cv);
            atomicAdd(&g_cnt_lt, clt);
            if (ceq) atomicAdd(&g_cnt_eq, ceq);
        }
    }

    // last-block-done: decision epilogue + state reset for the next replay
    __shared__ bool s_last;
    if (threadIdx.x == 0) {
        __threadfence();
        unsigned t = atomicAdd(&g_done, 1u);
        s_last = (t == gridDim.x - 1);
    }
    __syncthreads();
    if (s_last && threadIdx.x == 0) {
        g_done = 0u;
        long long nv = (long long)g_cnt_valid;
        long long k  = nv - 1;
        if (k > (long long)MIN_KEPT) k = MIN_KEPT;
        long long lt = (long long)g_cnt_lt;
        // sort_p[k] <= 0.7  <=>  count(valid & p <= 0.7) >= k+1 => threshold == 0.7
        if (lt + (long long)g_cnt_eq >= k + 1) {
            out[0] = (float)(g_sum_lt / (double)lt);
            g_sum_lt = 0.0; g_cnt_lt = 0;          // hot path: reset now
            // g_flag stays 0
        } else {
            g_flag = 1;
            g_rank_hi = (int)(k - lt);             // rank within p >= 0.7 region
            // g_sum_lt / g_cnt_lt kept alive for k_refine, which resets them
        }
        g_cnt_valid = 0; g_cnt_eq = 0;
    }
}

// -------- refinement path: ONE single-block kernel, early-exits on flag ------
// Never taken for the benchmark distribution (threshold saturates at 0.7),
// so its only hot-path cost is one near-empty launch. If taken, it computes
// the exact k-th smallest p >= 0.7 via a two-level 16-bit radix histogram and
// the [0.7, T) loss band, serially from one block (correct, slow, irrelevant).
__global__ void __launch_bounds__(1024) k_refine(
    const float* __restrict__ P, const float* __restrict__ T,
    const float* __restrict__ W, float* __restrict__ out, int n)
{
    if (!g_flag) return;                 // uniform: safe w.r.t. barriers below
    const int tid = threadIdx.x;
    const int nt  = blockDim.x;

    // phase 0: zero histograms
    for (int j = tid; j < 65536; j += nt) { g_hist_hi[j] = 0u; g_hist_lo[j] = 0u; }
    __syncthreads();

    // phase 1: high-16-bit histogram of valid p >= 0.7
    for (int i = tid; i < n; i += nt) {
        float tv = T[i], pv = P[i];
        if (tv != IGNORE_LBL && pv >= THRESH)
            atomicAdd(&g_hist_hi[__float_as_uint(pv) >> 16], 1u);
    }
    __syncthreads();

    __shared__ unsigned s_bin;
    __shared__ int      s_rlo;
    if (tid == 0) {
        unsigned cum = 0, r = (unsigned)g_rank_hi;
        for (int b = 0; b < 65536; b++) {
            unsigned c = g_hist_hi[b];
            if (cum + c > r) { s_bin = (unsigned)b; s_rlo = (int)(r - cum); break; }
            cum += c;
        }
    }
    __syncthreads();

    // phase 2: low-16-bit histogram within the winning bin
    unsigned bh = s_bin;
    for (int i = tid; i < n; i += nt) {
        float tv = T[i], pv = P[i];
        if (tv != IGNORE_LBL && pv >= THRESH) {
            unsigned b = __float_as_uint(pv);
            if ((b >> 16) == bh) atomicAdd(&g_hist_lo[b & 0xFFFFu], 1u);
        }
    }
    __syncthreads();

    __shared__ float s_T;
    if (tid == 0) {
        unsigned cum = 0, r = (unsigned)s_rlo;
        for (int l = 0; l < 65536; l++) {
            unsigned c = g_hist_lo[l];
            if (cum + c > r) { s_T = __uint_as_float((bh << 16) | (unsigned)l); break; }
            cum += c;
        }
    }
    __syncthreads();

    // phase 3: loss over the [0.7, T) band
    float Tv = s_T;
    float sum = 0.0f; int cnt = 0;
    for (int i = tid; i < n; i += nt) {
        float tv = T[i], pv = P[i];
        if (tv != IGNORE_LBL && pv >= THRESH && pv < Tv) {
            sum += bce(pv, tv, W[i]);
            cnt++;
        }
    }
    const unsigned full = 0xFFFFFFFFu;
    for (int o = 16; o; o >>= 1) {
        sum += __shfl_down_sync(full, sum, o);
        cnt += __shfl_down_sync(full, cnt, o);
    }
    __shared__ float ss[32];
    __shared__ int   sc[32];
    int lane = tid & 31, wid = tid >> 5;
    if (lane == 0) { ss[wid] = sum; sc[wid] = cnt; }
    __syncthreads();
    if (wid == 0) {
        int nw = nt >> 5;
        sum = (lane < nw) ? ss[lane] : 0.0f;
        cnt = (lane < nw) ? sc[lane] : 0;
        for (int o = 16; o; o >>= 1) {
            sum += __shfl_down_sync(full, sum, o);
            cnt += __shfl_down_sync(full, cnt, o);
        }
        if (lane == 0) {
            out[0] = (float)((g_sum_lt + (double)sum) / (double)(g_cnt_lt + cnt));
            // reset everything for the next replay
            g_sum_lt = 0.0; g_cnt_lt = 0; g_flag = 0; g_rank_hi = 0;
        }
    }
}

// ------------------------------- launcher -----------------------------------
extern "C" void kernel_launch(void* const* d_in, const int* in_sizes, int n_in,
                              void* d_out, int out_size)
{
    const float* P = (const float*)d_in[0];   // predict
    const float* T = (const float*)d_in[1];   // target
    const float* W = (const float*)d_in[2];   // weight
    float* out = (float*)d_out;
    int n = in_sizes[0];

    int nvec = n >> 2;
    int blocks = (nvec + 255) / 256;
    if (blocks > 8192) blocks = 8192;
    if (blocks < 1) blocks = 1;

    k_pass1<<<blocks, 256>>>(P, T, W, out, n);
    k_refine<<<1, 1024>>>(P, T, W, out, n);
}